// round 9
// baseline (speedup 1.0000x reference)
#include <cuda_runtime.h>
#include <cuda_fp16.h>
#include <cstdint>

// ============================================================================
// GraphConstructionActorHead — all N*N pair scores via factored 3-layer MLP.
//   pre: A[i]=emb_i@W1[:64]+b1 (row-major), B[j]=emb_j@W1[64:] in transposed
//     column-tile layout (coalesced per-pair reads); per-node (sum,sumsq);
//     W2^T fp16 swizzled; packed LN/epilogue consts -> __constant__.
//   main: tile = 128 pairs (one i, 128 j). Warp owns 32 rows end-to-end.
//     Two-pass layer 1 (pass1: A·B dot for LN stats; pass2: stream x->h->fp16
//     ->smem, reloading L1-hot lines) -> ldmatrix -> single-pass fp16 mma.sync
//     (W2 frags streamed from smem) -> LN2 + W3 dot on fragments (shfl, const
//     cache) -> coalesced store.
//   4 CTAs/SM (regs<=128 via two-pass + streamed W2), single wave.
// ============================================================================

#define NN 1024
#define NUM_TILES 8192
#define GRID_MAIN 608              // 4 CTAs/SM * 152 SMs, single wave
#define SMEM_BYTES 25600

// ---------------- device scratch --------------------------------------------
__device__ float g_A[NN * 64];
__device__ float g_Bt[NN * 64];             // [jb][16 quads][128 rows][4]
__device__ float2 g_stA[NN];
__device__ float2 g_stB[NN];
__device__ __half g_w2hi[64 * 64];          // [n][k] rows of 128B, XOR-swizzled
__device__ float4 g_gb1d[32];               // staging for constant copies
__device__ float4 g_epid[64];

__constant__ float4 c_gb1[32];              // (g1[2t],be1[2t],g1[2t+1],be1[2t+1])
__constant__ float4 c_epi[64];              // per col: (g2, be2, W3, b2)

// ---------------- PTX helpers (family-common only) --------------------------
__device__ __forceinline__ uint32_t smem_to_u32(const void* p) {
    uint32_t a;
    asm("{ .reg .u64 t; cvta.to.shared.u64 t, %1; cvt.u32.u64 %0, t; }"
        : "=r"(a) : "l"(p));
    return a;
}
__device__ __forceinline__ void ldm_x4(uint32_t* r, uint32_t addr) {
    asm volatile("ldmatrix.sync.aligned.m8n8.x4.shared.b16 {%0,%1,%2,%3}, [%4];"
                 : "=r"(r[0]), "=r"(r[1]), "=r"(r[2]), "=r"(r[3]) : "r"(addr));
}
__device__ __forceinline__ void mma_f16(float* c, const uint32_t* a,
                                        uint32_t b0, uint32_t b1) {
    asm volatile(
        "mma.sync.aligned.m16n8k16.row.col.f32.f16.f16.f32 "
        "{%0,%1,%2,%3}, {%4,%5,%6,%7}, {%8,%9}, {%0,%1,%2,%3};"
        : "+f"(c[0]), "+f"(c[1]), "+f"(c[2]), "+f"(c[3])
        : "r"(a[0]), "r"(a[1]), "r"(a[2]), "r"(a[3]), "r"(b0), "r"(b1));
}
__device__ __forceinline__ int swz(int row, int chunk) {
    return row * 128 + ((chunk ^ (row & 7)) << 4);
}

// ---------------- merged precompute (1 launch, 130 blocks x 512) ------------
__global__ void precompute_all(const float* __restrict__ emb,
                               const float* __restrict__ W1,
                               const float* __restrict__ b1,
                               const float* __restrict__ W2,
                               const float* __restrict__ g1, const float* __restrict__ be1,
                               const float* __restrict__ g2, const float* __restrict__ be2,
                               const float* __restrict__ W3, const float* __restrict__ b2) {
    int bid = blockIdx.x;
    int tid = threadIdx.x;
    if (bid < 128) {
        __shared__ float e[8][64];
        __shared__ float part[8][2][4];
        int g = tid >> 6, h = tid & 63;
        int n = bid * 8 + g;
        e[g][h] = emb[n * 64 + h];
        __syncthreads();
        float a0 = b1[h], a1 = 0.f, c0 = 0.f, c1 = 0.f;
#pragma unroll
        for (int d = 0; d < 64; d += 2) {
            float e0 = e[g][d], e1 = e[g][d + 1];
            a0 = fmaf(e0, __ldg(W1 + d * 64 + h), a0);
            a1 = fmaf(e1, __ldg(W1 + (d + 1) * 64 + h), a1);
            c0 = fmaf(e0, __ldg(W1 + (64 + d) * 64 + h), c0);
            c1 = fmaf(e1, __ldg(W1 + (65 + d) * 64 + h), c1);
        }
        float a = a0 + a1, b = c0 + c1;
        g_A[n * 64 + h] = a;
        g_Bt[(((n >> 7) * 16 + (h >> 2)) * 128 + (n & 127)) * 4 + (h & 3)] = b;
        float sa = a, qa = a * a, sb = b, qb = b * b;
#pragma unroll
        for (int o = 16; o > 0; o >>= 1) {
            sa += __shfl_xor_sync(0xffffffffu, sa, o);
            qa += __shfl_xor_sync(0xffffffffu, qa, o);
            sb += __shfl_xor_sync(0xffffffffu, sb, o);
            qb += __shfl_xor_sync(0xffffffffu, qb, o);
        }
        int w = (tid >> 5) & 1;
        if ((tid & 31) == 0) {
            part[g][w][0] = sa; part[g][w][1] = qa;
            part[g][w][2] = sb; part[g][w][3] = qb;
        }
        __syncthreads();
        if (tid < 8) {
            int nn = bid * 8 + tid;
            g_stA[nn] = make_float2(part[tid][0][0] + part[tid][1][0],
                                    part[tid][0][1] + part[tid][1][1]);
            g_stB[nn] = make_float2(part[tid][0][2] + part[tid][1][2],
                                    part[tid][0][3] + part[tid][1][3]);
        }
    } else if (bid == 128) {
#pragma unroll
        for (int u = 0; u < 8; u++) {
            int idx = tid + 512 * u;               // 0..4095
            int k = idx >> 6, n = idx & 63;
            float v = W2[k * 64 + n];              // B[n][k] = W2[k][n]
            int byte = swz(n, k >> 3) + (k & 7) * 2;
            g_w2hi[byte >> 1] = __float2half_rn(v);
        }
    } else {
        if (tid < 32) g_gb1d[tid] = make_float4(g1[2 * tid], be1[2 * tid],
                                                g1[2 * tid + 1], be1[2 * tid + 1]);
        if (tid < 64) g_epid[tid] = make_float4(g2[tid], be2[tid], W3[tid], b2[tid]);
    }
}

// ---------------- main fused pair-MLP kernel --------------------------------
__global__ void __launch_bounds__(128, 4) pair_mlp_kernel(
    const float* __restrict__ mask, const float* __restrict__ b3p,
    float* __restrict__ out) {
    extern __shared__ char smem_raw[];
    uint32_t smem_u = smem_to_u32(smem_raw);
    uint32_t base = (smem_u + 1023) & ~1023u;
    char* basep = smem_raw + (base - smem_u);

    const uint32_t OFF_AHI = 0;        // h1 fp16 [128 rows x 128B] 16 KB
    const uint32_t OFF_BHI = 16384;    // W2^T fp16 [64 x 128B]      8 KB

    int tid = threadIdx.x;
    int l = tid & 31;
    int wb = (tid >> 5) << 5;          // warp's 32-row slice base

    // copy pre-swizzled W2 into smem (startup only)
    {
        uint4* ph = (uint4*)(basep + OFF_BHI);
        const uint4* shi = (const uint4*)g_w2hi;
#pragma unroll
        for (int t = 0; t < 4; t++) ph[tid + 128 * t] = __ldg(shi + tid + 128 * t);
    }
    __syncthreads();

    float b3 = __ldg(b3p);
    int arow_lo = ((l >> 3) & 1) * 8 + (l & 7);
    int asel = l >> 4;
    int brow = (l & 7);
    int bnb_hi = (l >> 4) & 1;
    int bchunk = (l >> 3) & 1;
    int c4 = l & 3;

    // chunked schedule: consecutive tiles share jbase -> Bt block L1-resident
    int t0 = (int)(((long long)blockIdx.x * NUM_TILES) / GRID_MAIN);
    int t1 = (int)(((long long)(blockIdx.x + 1) * NUM_TILES) / GRID_MAIN);

    for (int T = t0; T < t1; T++) {
        int i = T & 1023;
        int jbase = (T >> 10) << 7;
        int j = jbase + tid;

        const float4* Ar = (const float4*)(g_A + i * 64);
        const float4* Br = (const float4*)g_Bt + (size_t)(T >> 10) * 2048 + tid;

        // ---- pass 1: A·B dot only (LN stats via precomputed node stats) ----
        float d0 = 0, d1 = 0, d2 = 0, d3 = 0;
#pragma unroll
        for (int t = 0; t < 16; t++) {
            float4 a = __ldg(Ar + t);
            float4 b = __ldg(Br + t * 128);        // coalesced: lane = row
            d0 = fmaf(a.x, b.x, d0); d1 = fmaf(a.y, b.y, d1);
            d2 = fmaf(a.z, b.z, d2); d3 = fmaf(a.w, b.w, d3);
        }
        float2 stA = __ldg(g_stA + i);
        float2 stB = __ldg(g_stB + j);
        float dot = (d0 + d1) + (d2 + d3);
        float m  = (stA.x + stB.x) * (1.f / 64.f);
        float v  = (stA.y + stB.y + 2.f * dot) * (1.f / 64.f) - m * m;
        float rs = rsqrtf(v + 1e-5f);
        float nm = -m * rs;

        // ---- pass 2: reload (L1-hot), LN1+ReLU, fp16, STS ------------------
#pragma unroll
        for (int c = 0; c < 8; c++) {
            float4 a0 = __ldg(Ar + 2 * c);
            float4 b0 = __ldg(Br + (2 * c) * 128);
            float4 a1 = __ldg(Ar + 2 * c + 1);
            float4 b1 = __ldg(Br + (2 * c + 1) * 128);
            float xs[8] = {a0.x + b0.x, a0.y + b0.y, a0.z + b0.z, a0.w + b0.w,
                           a1.x + b1.x, a1.y + b1.y, a1.z + b1.z, a1.w + b1.w};
            uint32_t hiw[4];
#pragma unroll
            for (int u = 0; u < 4; u++) {
                float4 gb = c_gb1[4 * c + u];      // uniform -> const port
                float u0 = fmaf(xs[2 * u], rs, nm);
                float u1 = fmaf(xs[2 * u + 1], rs, nm);
                float h0 = fmaxf(fmaf(u0, gb.x, gb.y), 0.f);
                float h1 = fmaxf(fmaf(u1, gb.z, gb.w), 0.f);
                __half2 hv = __floats2half2_rn(h0, h1);
                hiw[u] = *(uint32_t*)&hv;
            }
            int off = swz(tid, c);
            *(uint4*)(basep + OFF_AHI + off) = make_uint4(hiw[0], hiw[1], hiw[2], hiw[3]);
        }
        __syncwarp();   // warp-private rows: only intra-warp visibility needed

        // ---- layer 2 GEMM: single-pass fp16, W2 frags streamed from smem ---
        float acc[2][8][4] = {};
#pragma unroll
        for (int kc = 0; kc < 4; kc++) {
            uint32_t ahi0[4], ahi1[4];
            ldm_x4(ahi0, base + OFF_AHI + swz(wb + arow_lo, kc * 2 + asel));
            ldm_x4(ahi1, base + OFF_AHI + swz(wb + 16 + arow_lo, kc * 2 + asel));
#pragma unroll
            for (int p = 0; p < 4; p++) {
                uint32_t r[4];
                ldm_x4(r, base + OFF_BHI +
                           swz((2 * p + bnb_hi) * 8 + brow, kc * 2 + bchunk));
                mma_f16(acc[0][2 * p],     ahi0, r[0], r[1]);
                mma_f16(acc[1][2 * p],     ahi1, r[0], r[1]);
                mma_f16(acc[0][2 * p + 1], ahi0, r[2], r[3]);
                mma_f16(acc[1][2 * p + 1], ahi1, r[2], r[3]);
            }
        }

        // ---- epilogue: +b2, LN2 stats (shfl), ReLU, dot W3 -----------------
#pragma unroll
        for (int nb = 0; nb < 8; nb++) {
            float w0 = c_epi[nb * 8 + 2 * c4].w;
            float w1 = c_epi[nb * 8 + 2 * c4 + 1].w;
            acc[0][nb][0] += w0; acc[0][nb][1] += w1;
            acc[0][nb][2] += w0; acc[0][nb][3] += w1;
            acc[1][nb][0] += w0; acc[1][nb][1] += w1;
            acc[1][nb][2] += w0; acc[1][nb][3] += w1;
        }
        float rs0[2], nm0[2], rs1[2], nm1[2];
#pragma unroll
        for (int mf = 0; mf < 2; mf++) {
            float su0 = 0, qu0 = 0, su1 = 0, qu1 = 0;
#pragma unroll
            for (int nb = 0; nb < 8; nb++) {
                float a0 = acc[mf][nb][0], a1 = acc[mf][nb][1];
                float a2 = acc[mf][nb][2], a3 = acc[mf][nb][3];
                su0 += a0 + a1; qu0 = fmaf(a0, a0, fmaf(a1, a1, qu0));
                su1 += a2 + a3; qu1 = fmaf(a2, a2, fmaf(a3, a3, qu1));
            }
            su0 += __shfl_xor_sync(0xffffffffu, su0, 1);
            su0 += __shfl_xor_sync(0xffffffffu, su0, 2);
            qu0 += __shfl_xor_sync(0xffffffffu, qu0, 1);
            qu0 += __shfl_xor_sync(0xffffffffu, qu0, 2);
            su1 += __shfl_xor_sync(0xffffffffu, su1, 1);
            su1 += __shfl_xor_sync(0xffffffffu, su1, 2);
            qu1 += __shfl_xor_sync(0xffffffffu, qu1, 1);
            qu1 += __shfl_xor_sync(0xffffffffu, qu1, 2);
            float m0 = su0 * (1.f / 64.f);
            float v0 = qu0 * (1.f / 64.f) - m0 * m0;
            rs0[mf] = rsqrtf(v0 + 1e-5f); nm0[mf] = -m0 * rs0[mf];
            float m1 = su1 * (1.f / 64.f);
            float v1 = qu1 * (1.f / 64.f) - m1 * m1;
            rs1[mf] = rsqrtf(v1 + 1e-5f); nm1[mf] = -m1 * rs1[mf];
        }

        float w00 = 0, w01 = 0, w10 = 0, w11 = 0;
#pragma unroll
        for (int nb = 0; nb < 8; nb++) {
            float4 e0 = c_epi[nb * 8 + 2 * c4];
            float4 e1 = c_epi[nb * 8 + 2 * c4 + 1];
            float y;
            y = fmaxf(fmaf(fmaf(acc[0][nb][0], rs0[0], nm0[0]), e0.x, e0.y), 0.f);
            w00 = fmaf(y, e0.z, w00);
            y = fmaxf(fmaf(fmaf(acc[0][nb][1], rs0[0], nm0[0]), e1.x, e1.y), 0.f);
            w00 = fmaf(y, e1.z, w00);
            y = fmaxf(fmaf(fmaf(acc[0][nb][2], rs1[0], nm1[0]), e0.x, e0.y), 0.f);
            w01 = fmaf(y, e0.z, w01);
            y = fmaxf(fmaf(fmaf(acc[0][nb][3], rs1[0], nm1[0]), e1.x, e1.y), 0.f);
            w01 = fmaf(y, e1.z, w01);
            y = fmaxf(fmaf(fmaf(acc[1][nb][0], rs0[1], nm0[1]), e0.x, e0.y), 0.f);
            w10 = fmaf(y, e0.z, w10);
            y = fmaxf(fmaf(fmaf(acc[1][nb][1], rs0[1], nm0[1]), e1.x, e1.y), 0.f);
            w10 = fmaf(y, e1.z, w10);
            y = fmaxf(fmaf(fmaf(acc[1][nb][2], rs1[1], nm1[1]), e0.x, e0.y), 0.f);
            w11 = fmaf(y, e0.z, w11);
            y = fmaxf(fmaf(fmaf(acc[1][nb][3], rs1[1], nm1[1]), e1.x, e1.y), 0.f);
            w11 = fmaf(y, e1.z, w11);
        }
        w00 += __shfl_xor_sync(0xffffffffu, w00, 1);
        w00 += __shfl_xor_sync(0xffffffffu, w00, 2);
        w01 += __shfl_xor_sync(0xffffffffu, w01, 1);
        w01 += __shfl_xor_sync(0xffffffffu, w01, 2);
        w10 += __shfl_xor_sync(0xffffffffu, w10, 1);
        w10 += __shfl_xor_sync(0xffffffffu, w10, 2);
        w11 += __shfl_xor_sync(0xffffffffu, w11, 1);
        w11 += __shfl_xor_sync(0xffffffffu, w11, 2);

        // gather so lane l holds row wb+l -> coalesced mask load + store
        int src = (l & 7) * 4;
        float a0 = __shfl_sync(0xffffffffu, w00, src);
        float a1 = __shfl_sync(0xffffffffu, w01, src);
        float a2 = __shfl_sync(0xffffffffu, w10, src);
        float a3 = __shfl_sync(0xffffffffu, w11, src);
        float dv = (l < 8) ? a0 : (l < 16) ? a1 : (l < 24) ? a2 : a3;
        int jj = jbase + wb + l;
        int p = (i << 10) + jj;
        float sc = (dv + b3) * __ldg(mask + p);
        out[p] = (jj == i) ? 0.f : sc;

        __syncwarp();   // lanes rejoin before next tile's STS to the warp slice
    }
}

// ---------------- launch ----------------------------------------------------
extern "C" void kernel_launch(void* const* d_in, const int* in_sizes, int n_in,
                              void* d_out, int out_size) {
    const float* emb  = (const float*)d_in[0];
    const float* mask = (const float*)d_in[1];
    const float* W1   = (const float*)d_in[2];
    const float* b1   = (const float*)d_in[3];
    const float* g1   = (const float*)d_in[4];
    const float* be1  = (const float*)d_in[5];
    const float* W2   = (const float*)d_in[6];
    const float* b2   = (const float*)d_in[7];
    const float* g2   = (const float*)d_in[8];
    const float* be2  = (const float*)d_in[9];
    const float* W3   = (const float*)d_in[10];
    const float* b3   = (const float*)d_in[11];
    float* out = (float*)d_out;

    cudaFuncSetAttribute(pair_mlp_kernel,
                         cudaFuncAttributeMaxDynamicSharedMemorySize, SMEM_BYTES);

    precompute_all<<<130, 512>>>(emb, W1, b1, W2, g1, be1, g2, be2, W3, b2);

    // stage packed consts into __constant__ (async D2D copies, capturable)
    void* pgb = nullptr; void* pep = nullptr;
    cudaGetSymbolAddress(&pgb, g_gb1d);
    cudaGetSymbolAddress(&pep, g_epid);
    cudaMemcpyToSymbolAsync(c_gb1, pgb, 32 * sizeof(float4), 0,
                            cudaMemcpyDeviceToDevice, 0);
    cudaMemcpyToSymbolAsync(c_epi, pep, 64 * sizeof(float4), 0,
                            cudaMemcpyDeviceToDevice, 0);

    pair_mlp_kernel<<<GRID_MAIN, 128, SMEM_BYTES>>>(mask, b3, out);
}

// round 11
// speedup vs baseline: 1.2998x; 1.2998x over previous
#include <cuda_runtime.h>
#include <cuda_fp16.h>
#include <cstdint>

// ============================================================================
// GraphConstructionActorHead — all N*N pair scores via factored 3-layer MLP.
//   pre: A[i]=emb_i@W1[:64]+b1, B[j]=emb_j@W1[64:] in transposed column-tile
//     layout; per-node (sum,sumsq); W2^T fp16 swizzled; LN1 g/be + W3 packed
//     half2 -> __constant__; epilogue float4 consts -> __constant__.
//   main: tile = 128 pairs (one i, 128 j). Warp owns 32 rows end-to-end.
//     layer1: fp32 dot for LN stats, x kept as 32 half2 regs, LN1+ReLU in
//     HFMA2/HMAX2 -> smem -> ldmatrix -> single-pass fp16 mma.sync ->
//     LN2 stats (shfl) -> y in fp16 -> W3 dot via mma.sync (A-frag == D-frag
//     layout identity; b3 in accumulator init) -> coalesced store.
//   4 CTAs/SM, single wave, chunked schedule.
// ============================================================================

#define NN 1024
#define NUM_TILES 8192
#define GRID_MAIN 608              // 4 CTAs/SM * 152 SMs, single wave
#define SMEM_BYTES 25600

// ---------------- device scratch --------------------------------------------
__device__ float g_A[NN * 64];
__device__ float g_Bt[NN * 64];             // [jb][16 quads][128 rows][4]
__device__ float2 g_stA[NN];
__device__ float2 g_stB[NN];
__device__ __half g_w2hi[64 * 64];          // [n][k] rows of 128B, XOR-swizzled
__device__ uint32_t g_h2d[96];              // staging: g1h[32] be1h[32] w3h[32]
__device__ float4 g_epid[64];               // staging: (g2, be2, W3, b2)

__constant__ uint32_t c_h2[96];
__constant__ float4 c_epi[64];

// ---------------- PTX helpers (family-common only) --------------------------
__device__ __forceinline__ uint32_t smem_to_u32(const void* p) {
    uint32_t a;
    asm("{ .reg .u64 t; cvta.to.shared.u64 t, %1; cvt.u32.u64 %0, t; }"
        : "=r"(a) : "l"(p));
    return a;
}
__device__ __forceinline__ void ldm_x4(uint32_t* r, uint32_t addr) {
    asm volatile("ldmatrix.sync.aligned.m8n8.x4.shared.b16 {%0,%1,%2,%3}, [%4];"
                 : "=r"(r[0]), "=r"(r[1]), "=r"(r[2]), "=r"(r[3]) : "r"(addr));
}
__device__ __forceinline__ void mma_f16(float* c, const uint32_t* a,
                                        uint32_t b0, uint32_t b1) {
    asm volatile(
        "mma.sync.aligned.m16n8k16.row.col.f32.f16.f16.f32 "
        "{%0,%1,%2,%3}, {%4,%5,%6,%7}, {%8,%9}, {%0,%1,%2,%3};"
        : "+f"(c[0]), "+f"(c[1]), "+f"(c[2]), "+f"(c[3])
        : "r"(a[0]), "r"(a[1]), "r"(a[2]), "r"(a[3]), "r"(b0), "r"(b1));
}
__device__ __forceinline__ int swz(int row, int chunk) {
    return row * 128 + ((chunk ^ (row & 7)) << 4);
}
__device__ __forceinline__ uint32_t h2bits(__half2 h) { return *(uint32_t*)&h; }
__device__ __forceinline__ __half2 bits2h(uint32_t u) { return *(__half2*)&u; }

// ---------------- merged precompute (1 launch, 130 blocks x 512) ------------
__global__ void precompute_all(const float* __restrict__ emb,
                               const float* __restrict__ W1,
                               const float* __restrict__ b1,
                               const float* __restrict__ W2,
                               const float* __restrict__ g1, const float* __restrict__ be1,
                               const float* __restrict__ g2, const float* __restrict__ be2,
                               const float* __restrict__ W3, const float* __restrict__ b2) {
    int bid = blockIdx.x;
    int tid = threadIdx.x;
    if (bid < 128) {
        __shared__ float e[8][64];
        __shared__ float part[8][2][4];
        int g = tid >> 6, h = tid & 63;
        int n = bid * 8 + g;
        e[g][h] = emb[n * 64 + h];
        __syncthreads();
        float a0 = b1[h], a1 = 0.f, c0 = 0.f, c1 = 0.f;
#pragma unroll
        for (int d = 0; d < 64; d += 2) {
            float e0 = e[g][d], e1 = e[g][d + 1];
            a0 = fmaf(e0, __ldg(W1 + d * 64 + h), a0);
            a1 = fmaf(e1, __ldg(W1 + (d + 1) * 64 + h), a1);
            c0 = fmaf(e0, __ldg(W1 + (64 + d) * 64 + h), c0);
            c1 = fmaf(e1, __ldg(W1 + (65 + d) * 64 + h), c1);
        }
        float a = a0 + a1, b = c0 + c1;
        g_A[n * 64 + h] = a;
        g_Bt[(((n >> 7) * 16 + (h >> 2)) * 128 + (n & 127)) * 4 + (h & 3)] = b;
        float sa = a, qa = a * a, sb = b, qb = b * b;
#pragma unroll
        for (int o = 16; o > 0; o >>= 1) {
            sa += __shfl_xor_sync(0xffffffffu, sa, o);
            qa += __shfl_xor_sync(0xffffffffu, qa, o);
            sb += __shfl_xor_sync(0xffffffffu, sb, o);
            qb += __shfl_xor_sync(0xffffffffu, qb, o);
        }
        int w = (tid >> 5) & 1;
        if ((tid & 31) == 0) {
            part[g][w][0] = sa; part[g][w][1] = qa;
            part[g][w][2] = sb; part[g][w][3] = qb;
        }
        __syncthreads();
        if (tid < 8) {
            int nn = bid * 8 + tid;
            g_stA[nn] = make_float2(part[tid][0][0] + part[tid][1][0],
                                    part[tid][0][1] + part[tid][1][1]);
            g_stB[nn] = make_float2(part[tid][0][2] + part[tid][1][2],
                                    part[tid][0][3] + part[tid][1][3]);
        }
    } else if (bid == 128) {
#pragma unroll
        for (int u = 0; u < 8; u++) {
            int idx = tid + 512 * u;               // 0..4095
            int k = idx >> 6, n = idx & 63;
            float v = W2[k * 64 + n];              // B[n][k] = W2[k][n]
            int byte = swz(n, k >> 3) + (k & 7) * 2;
            g_w2hi[byte >> 1] = __float2half_rn(v);
        }
    } else {
        if (tid < 32) {
            g_h2d[tid] = h2bits(__floats2half2_rn(g1[2 * tid], g1[2 * tid + 1]));
            g_h2d[32 + tid] = h2bits(__floats2half2_rn(be1[2 * tid], be1[2 * tid + 1]));
            g_h2d[64 + tid] = h2bits(__floats2half2_rn(W3[2 * tid], W3[2 * tid + 1]));
        }
        if (tid < 64) g_epid[tid] = make_float4(g2[tid], be2[tid], W3[tid], b2[tid]);
    }
}

// ---------------- main fused pair-MLP kernel --------------------------------
__global__ void __launch_bounds__(128, 4) pair_mlp_kernel(
    const float* __restrict__ mask, const float* __restrict__ b3p,
    float* __restrict__ out) {
    extern __shared__ char smem_raw[];
    uint32_t smem_u = smem_to_u32(smem_raw);
    uint32_t base = (smem_u + 1023) & ~1023u;
    char* basep = smem_raw + (base - smem_u);

    const uint32_t OFF_AHI = 0;        // h1 fp16 [128 rows x 128B] 16 KB
    const uint32_t OFF_BHI = 16384;    // W2^T fp16 [64 x 128B]      8 KB

    int tid = threadIdx.x;
    int l = tid & 31;
    int wb = (tid >> 5) << 5;          // warp's 32-row slice base

    // copy pre-swizzled W2 into smem (startup only)
    {
        uint4* ph = (uint4*)(basep + OFF_BHI);
        const uint4* shi = (const uint4*)g_w2hi;
#pragma unroll
        for (int t = 0; t < 4; t++) ph[tid + 128 * t] = __ldg(shi + tid + 128 * t);
    }
    __syncthreads();

    float b3 = __ldg(b3p);
    int arow_lo = ((l >> 3) & 1) * 8 + (l & 7);
    int asel = l >> 4;
    int brow = (l & 7);
    int bnb_hi = (l >> 4) & 1;
    int bchunk = (l >> 3) & 1;
    int c4 = l & 3;

    // W3 B-fragments (constant per lane, resident): replicated across n so
    // output column 0 carries the true dot
    uint32_t w3f0[4], w3f1[4];
#pragma unroll
    for (int p = 0; p < 4; p++) {
        w3f0[p] = c_h2[64 + 8 * p + c4];
        w3f1[p] = c_h2[64 + 8 * p + c4 + 4];
    }

    // chunked schedule: consecutive tiles share jbase -> Bt block L1-resident
    int t0 = (int)(((long long)blockIdx.x * NUM_TILES) / GRID_MAIN);
    int t1 = (int)(((long long)(blockIdx.x + 1) * NUM_TILES) / GRID_MAIN);

    for (int T = t0; T < t1; T++) {
        int i = T & 1023;
        int jbase = (T >> 10) << 7;

        const float4* Ar = (const float4*)(g_A + i * 64);
        const float4* Br = (const float4*)g_Bt + (size_t)(T >> 10) * 2048 + tid;

        // ---- layer 1: fp32 dot for stats; x packed to half2 regs -----------
        float d0 = 0, d1 = 0, d2 = 0, d3 = 0;
        uint32_t xh[32];
#pragma unroll
        for (int t = 0; t < 16; t++) {
            float4 a = __ldg(Ar + t);
            float4 b = __ldg(Br + t * 128);        // coalesced: lane = row
            d0 = fmaf(a.x, b.x, d0); d1 = fmaf(a.y, b.y, d1);
            d2 = fmaf(a.z, b.z, d2); d3 = fmaf(a.w, b.w, d3);
            xh[2 * t]     = h2bits(__floats2half2_rn(a.x + b.x, a.y + b.y));
            xh[2 * t + 1] = h2bits(__floats2half2_rn(a.z + b.z, a.w + b.w));
        }
        float2 stA = __ldg(g_stA + i);
        float2 stB = __ldg(g_stB + jbase + tid);
        float dot = (d0 + d1) + (d2 + d3);
        float m  = (stA.x + stB.x) * (1.f / 64.f);
        float v  = (stA.y + stB.y + 2.f * dot) * (1.f / 64.f) - m * m;
        float rs = rsqrtf(v + 1e-5f);
        float nm = -m * rs;

        // LN1 + ReLU in half2, STS to warp-private rows
        __half2 rsh = __float2half2_rn(rs);
        __half2 nmh = __float2half2_rn(nm);
        __half2 z2 = __float2half2_rn(0.f);
#pragma unroll
        for (int c = 0; c < 8; c++) {
            uint32_t hiw[4];
#pragma unroll
            for (int u = 0; u < 4; u++) {
                int k2 = 4 * c + u;
                __half2 u0 = __hfma2(bits2h(xh[k2]), rsh, nmh);
                __half2 h = __hmax2(__hfma2(u0, bits2h(c_h2[k2]),
                                            bits2h(c_h2[32 + k2])), z2);
                hiw[u] = h2bits(h);
            }
            int off = swz(tid, c);
            *(uint4*)(basep + OFF_AHI + off) = make_uint4(hiw[0], hiw[1], hiw[2], hiw[3]);
        }
        __syncwarp();   // warp-private rows: only intra-warp visibility needed

        // ---- layer 2 GEMM: single-pass fp16, W2 frags streamed from smem ---
        float acc[2][8][4] = {};
#pragma unroll
        for (int kc = 0; kc < 4; kc++) {
            uint32_t ahi0[4], ahi1[4];
            ldm_x4(ahi0, base + OFF_AHI + swz(wb + arow_lo, kc * 2 + asel));
            ldm_x4(ahi1, base + OFF_AHI + swz(wb + 16 + arow_lo, kc * 2 + asel));
#pragma unroll
            for (int p = 0; p < 4; p++) {
                uint32_t r[4];
                ldm_x4(r, base + OFF_BHI +
                           swz((2 * p + bnb_hi) * 8 + brow, kc * 2 + bchunk));
                mma_f16(acc[0][2 * p],     ahi0, r[0], r[1]);
                mma_f16(acc[1][2 * p],     ahi1, r[0], r[1]);
                mma_f16(acc[0][2 * p + 1], ahi0, r[2], r[3]);
                mma_f16(acc[1][2 * p + 1], ahi1, r[2], r[3]);
            }
        }

        // ---- epilogue: +b2, LN2 stats (shfl) -------------------------------
#pragma unroll
        for (int nb = 0; nb < 8; nb++) {
            float w0 = c_epi[nb * 8 + 2 * c4].w;
            float w1 = c_epi[nb * 8 + 2 * c4 + 1].w;
            acc[0][nb][0] += w0; acc[0][nb][1] += w1;
            acc[0][nb][2] += w0; acc[0][nb][3] += w1;
            acc[1][nb][0] += w0; acc[1][nb][1] += w1;
            acc[1][nb][2] += w0; acc[1][nb][3] += w1;
        }
        float rs0[2], nm0[2], rs1[2], nm1[2];
#pragma unroll
        for (int mf = 0; mf < 2; mf++) {
            float su0 = 0, qu0 = 0, su1 = 0, qu1 = 0;
#pragma unroll
            for (int nb = 0; nb < 8; nb++) {
                float a0 = acc[mf][nb][0], a1 = acc[mf][nb][1];
                float a2 = acc[mf][nb][2], a3 = acc[mf][nb][3];
                su0 += a0 + a1; qu0 = fmaf(a0, a0, fmaf(a1, a1, qu0));
                su1 += a2 + a3; qu1 = fmaf(a2, a2, fmaf(a3, a3, qu1));
            }
            su0 += __shfl_xor_sync(0xffffffffu, su0, 1);
            su0 += __shfl_xor_sync(0xffffffffu, su0, 2);
            qu0 += __shfl_xor_sync(0xffffffffu, qu0, 1);
            qu0 += __shfl_xor_sync(0xffffffffu, qu0, 2);
            su1 += __shfl_xor_sync(0xffffffffu, su1, 1);
            su1 += __shfl_xor_sync(0xffffffffu, su1, 2);
            qu1 += __shfl_xor_sync(0xffffffffu, qu1, 1);
            qu1 += __shfl_xor_sync(0xffffffffu, qu1, 2);
            float m0 = su0 * (1.f / 64.f);
            float v0 = qu0 * (1.f / 64.f) - m0 * m0;
            rs0[mf] = rsqrtf(v0 + 1e-5f); nm0[mf] = -m0 * rs0[mf];
            float m1 = su1 * (1.f / 64.f);
            float v1 = qu1 * (1.f / 64.f) - m1 * m1;
            rs1[mf] = rsqrtf(v1 + 1e-5f); nm1[mf] = -m1 * rs1[mf];
        }

        // ---- y = relu(LN2) in fp16 -> W3 dot via mma (b3 in acc init) ------
        float w00, w01, w10, w11;
#pragma unroll
        for (int mf = 0; mf < 2; mf++) {
            float c2[4] = {b3, b3, b3, b3};
#pragma unroll
            for (int p = 0; p < 4; p++) {
                int nA = 2 * p, nB = 2 * p + 1;
                float4 eA0 = c_epi[nA * 8 + 2 * c4], eA1 = c_epi[nA * 8 + 2 * c4 + 1];
                float4 eB0 = c_epi[nB * 8 + 2 * c4], eB1 = c_epi[nB * 8 + 2 * c4 + 1];
                float yA0 = fmaxf(fmaf(fmaf(acc[mf][nA][0], rs0[mf], nm0[mf]), eA0.x, eA0.y), 0.f);
                float yA1 = fmaxf(fmaf(fmaf(acc[mf][nA][1], rs0[mf], nm0[mf]), eA1.x, eA1.y), 0.f);
                float yA2 = fmaxf(fmaf(fmaf(acc[mf][nA][2], rs1[mf], nm1[mf]), eA0.x, eA0.y), 0.f);
                float yA3 = fmaxf(fmaf(fmaf(acc[mf][nA][3], rs1[mf], nm1[mf]), eA1.x, eA1.y), 0.f);
                float yB0 = fmaxf(fmaf(fmaf(acc[mf][nB][0], rs0[mf], nm0[mf]), eB0.x, eB0.y), 0.f);
                float yB1 = fmaxf(fmaf(fmaf(acc[mf][nB][1], rs0[mf], nm0[mf]), eB1.x, eB1.y), 0.f);
                float yB2 = fmaxf(fmaf(fmaf(acc[mf][nB][2], rs1[mf], nm1[mf]), eB0.x, eB0.y), 0.f);
                float yB3 = fmaxf(fmaf(fmaf(acc[mf][nB][3], rs1[mf], nm1[mf]), eB1.x, eB1.y), 0.f);
                // A-frag == D-frag layout: rows {g,g+8}, k halves via nA/nB
                uint32_t af[4];
                af[0] = h2bits(__floats2half2_rn(yA0, yA1));
                af[1] = h2bits(__floats2half2_rn(yA2, yA3));
                af[2] = h2bits(__floats2half2_rn(yB0, yB1));
                af[3] = h2bits(__floats2half2_rn(yB2, yB3));
                mma_f16(c2, af, w3f0[p], w3f1[p]);
            }
            if (mf == 0) { w00 = c2[0]; w01 = c2[2]; }
            else         { w10 = c2[0]; w11 = c2[2]; }
        }

        // gather so lane l holds row wb+l -> coalesced mask load + store
        // (scores valid at c4==0 lanes; col 0 of the y@W3 product)
        int src = (l & 7) * 4;
        float a0 = __shfl_sync(0xffffffffu, w00, src);
        float a1 = __shfl_sync(0xffffffffu, w01, src);
        float a2 = __shfl_sync(0xffffffffu, w10, src);
        float a3 = __shfl_sync(0xffffffffu, w11, src);
        float dv = (l < 8) ? a0 : (l < 16) ? a1 : (l < 24) ? a2 : a3;
        int jj = jbase + wb + l;
        int p = (i << 10) + jj;
        float sc = dv * __ldg(mask + p);
        out[p] = (jj == i) ? 0.f : sc;

        __syncwarp();   // lanes rejoin before next tile's STS to the warp slice
    }
}

// ---------------- launch ----------------------------------------------------
extern "C" void kernel_launch(void* const* d_in, const int* in_sizes, int n_in,
                              void* d_out, int out_size) {
    const float* emb  = (const float*)d_in[0];
    const float* mask = (const float*)d_in[1];
    const float* W1   = (const float*)d_in[2];
    const float* b1   = (const float*)d_in[3];
    const float* g1   = (const float*)d_in[4];
    const float* be1  = (const float*)d_in[5];
    const float* W2   = (const float*)d_in[6];
    const float* b2   = (const float*)d_in[7];
    const float* g2   = (const float*)d_in[8];
    const float* be2  = (const float*)d_in[9];
    const float* W3   = (const float*)d_in[10];
    const float* b3   = (const float*)d_in[11];
    float* out = (float*)d_out;

    cudaFuncSetAttribute(pair_mlp_kernel,
                         cudaFuncAttributeMaxDynamicSharedMemorySize, SMEM_BYTES);

    precompute_all<<<130, 512>>>(emb, W1, b1, W2, g1, be1, g2, be2, W3, b2);

    // stage packed consts into __constant__ (async D2D copies, capturable)
    void* ph2 = nullptr; void* pep = nullptr;
    cudaGetSymbolAddress(&ph2, g_h2d);
    cudaGetSymbolAddress(&pep, g_epid);
    cudaMemcpyToSymbolAsync(c_h2, ph2, 96 * sizeof(uint32_t), 0,
                            cudaMemcpyDeviceToDevice, 0);
    cudaMemcpyToSymbolAsync(c_epi, pep, 64 * sizeof(float4), 0,
                            cudaMemcpyDeviceToDevice, 0);

    pair_mlp_kernel<<<GRID_MAIN, 128, SMEM_BYTES>>>(mask, b3, out);
}

// round 14
// speedup vs baseline: 1.4226x; 1.0945x over previous
#include <cuda_runtime.h>
#include <cuda_fp16.h>
#include <cstdint>

// ============================================================================
// GraphConstructionActorHead — all N*N pair scores via factored 3-layer MLP.
//   pre: A[i]=emb_i@W1[:64]+b1, B[j]=emb_j@W1[64:] in transposed column-tile
//     layout; per-node (sum,sumsq); W2^T fp16 swizzled; LN1/LN2 g,be + W3 as
//     packed half2 -> __constant__; b2 as packed float2 -> __constant__.
//   main: tile = 128 pairs (one i, 128 j). Warp owns 32 rows end-to-end.
//     layer1: fp32 dot for LN stats, x as 32 half2 regs, LN1+ReLU in HFMA2 ->
//     smem -> ldmatrix -> single-pass fp16 mma.sync (b2 in accumulator init)
//     -> LN2 stats fp32 (shfl) -> y via half2 HFMA2/HMAX2 -> W3 dot via
//     mma.sync (A-frag == D-frag layout identity; b3 in acc init) -> store.
//   4 CTAs/SM, single wave, chunked schedule.
// ============================================================================

#define NN 1024
#define NUM_TILES 8192
#define GRID_MAIN 608              // 4 CTAs/SM * 152 SMs, single wave
#define SMEM_BYTES 25600

// ---------------- device scratch --------------------------------------------
__device__ float g_A[NN * 64];
__device__ float g_Bt[NN * 64];             // [jb][16 quads][128 rows][4]
__device__ float2 g_stA[NN];
__device__ float2 g_stB[NN];
__device__ __half g_w2hi[64 * 64];          // [n][k] rows of 128B, XOR-swizzled
__device__ uint32_t g_h2d[160];             // staging: g1h be1h w3h g2h be2h
__device__ float2 g_b2d[32];                // staging: b2 pairs

__constant__ uint32_t c_h2[160];            // [0:32) g1h [32:64) be1h
                                            // [64:96) w3h [96:128) g2h
                                            // [128:160) be2h
__constant__ float2 c_b2[32];               // (b2[2k], b2[2k+1])

// ---------------- PTX helpers (family-common only) --------------------------
__device__ __forceinline__ uint32_t smem_to_u32(const void* p) {
    uint32_t a;
    asm("{ .reg .u64 t; cvta.to.shared.u64 t, %1; cvt.u32.u64 %0, t; }"
        : "=r"(a) : "l"(p));
    return a;
}
__device__ __forceinline__ void ldm_x4(uint32_t* r, uint32_t addr) {
    asm volatile("ldmatrix.sync.aligned.m8n8.x4.shared.b16 {%0,%1,%2,%3}, [%4];"
                 : "=r"(r[0]), "=r"(r[1]), "=r"(r[2]), "=r"(r[3]) : "r"(addr));
}
__device__ __forceinline__ void mma_f16(float* c, const uint32_t* a,
                                        uint32_t b0, uint32_t b1) {
    asm volatile(
        "mma.sync.aligned.m16n8k16.row.col.f32.f16.f16.f32 "
        "{%0,%1,%2,%3}, {%4,%5,%6,%7}, {%8,%9}, {%0,%1,%2,%3};"
        : "+f"(c[0]), "+f"(c[1]), "+f"(c[2]), "+f"(c[3])
        : "r"(a[0]), "r"(a[1]), "r"(a[2]), "r"(a[3]), "r"(b0), "r"(b1));
}
__device__ __forceinline__ int swz(int row, int chunk) {
    return row * 128 + ((chunk ^ (row & 7)) << 4);
}
__device__ __forceinline__ uint32_t h2bits(__half2 h) { return *(uint32_t*)&h; }
__device__ __forceinline__ __half2 bits2h(uint32_t u) { return *(__half2*)&u; }

// ---------------- merged precompute (1 launch, 130 blocks x 512) ------------
__global__ void precompute_all(const float* __restrict__ emb,
                               const float* __restrict__ W1,
                               const float* __restrict__ b1,
                               const float* __restrict__ W2,
                               const float* __restrict__ g1, const float* __restrict__ be1,
                               const float* __restrict__ g2, const float* __restrict__ be2,
                               const float* __restrict__ W3, const float* __restrict__ b2) {
    int bid = blockIdx.x;
    int tid = threadIdx.x;
    if (bid < 128) {
        __shared__ float e[8][64];
        __shared__ float part[8][2][4];
        int g = tid >> 6, h = tid & 63;
        int n = bid * 8 + g;
        e[g][h] = emb[n * 64 + h];
        __syncthreads();
        float a0 = b1[h], a1 = 0.f, c0 = 0.f, c1 = 0.f;
#pragma unroll
        for (int d = 0; d < 64; d += 2) {
            float e0 = e[g][d], e1 = e[g][d + 1];
            a0 = fmaf(e0, __ldg(W1 + d * 64 + h), a0);
            a1 = fmaf(e1, __ldg(W1 + (d + 1) * 64 + h), a1);
            c0 = fmaf(e0, __ldg(W1 + (64 + d) * 64 + h), c0);
            c1 = fmaf(e1, __ldg(W1 + (65 + d) * 64 + h), c1);
        }
        float a = a0 + a1, b = c0 + c1;
        g_A[n * 64 + h] = a;
        g_Bt[(((n >> 7) * 16 + (h >> 2)) * 128 + (n & 127)) * 4 + (h & 3)] = b;
        float sa = a, qa = a * a, sb = b, qb = b * b;
#pragma unroll
        for (int o = 16; o > 0; o >>= 1) {
            sa += __shfl_xor_sync(0xffffffffu, sa, o);
            qa += __shfl_xor_sync(0xffffffffu, qa, o);
            sb += __shfl_xor_sync(0xffffffffu, sb, o);
            qb += __shfl_xor_sync(0xffffffffu, qb, o);
        }
        int w = (tid >> 5) & 1;
        if ((tid & 31) == 0) {
            part[g][w][0] = sa; part[g][w][1] = qa;
            part[g][w][2] = sb; part[g][w][3] = qb;
        }
        __syncthreads();
        if (tid < 8) {
            int nn = bid * 8 + tid;
            g_stA[nn] = make_float2(part[tid][0][0] + part[tid][1][0],
                                    part[tid][0][1] + part[tid][1][1]);
            g_stB[nn] = make_float2(part[tid][0][2] + part[tid][1][2],
                                    part[tid][0][3] + part[tid][1][3]);
        }
    } else if (bid == 128) {
#pragma unroll
        for (int u = 0; u < 8; u++) {
            int idx = tid + 512 * u;               // 0..4095
            int k = idx >> 6, n = idx & 63;
            float v = W2[k * 64 + n];              // B[n][k] = W2[k][n]
            int byte = swz(n, k >> 3) + (k & 7) * 2;
            g_w2hi[byte >> 1] = __float2half_rn(v);
        }
    } else {
        if (tid < 32) {
            g_h2d[tid]       = h2bits(__floats2half2_rn(g1[2 * tid], g1[2 * tid + 1]));
            g_h2d[32 + tid]  = h2bits(__floats2half2_rn(be1[2 * tid], be1[2 * tid + 1]));
            g_h2d[64 + tid]  = h2bits(__floats2half2_rn(W3[2 * tid], W3[2 * tid + 1]));
            g_h2d[96 + tid]  = h2bits(__floats2half2_rn(g2[2 * tid], g2[2 * tid + 1]));
            g_h2d[128 + tid] = h2bits(__floats2half2_rn(be2[2 * tid], be2[2 * tid + 1]));
            g_b2d[tid]       = make_float2(b2[2 * tid], b2[2 * tid + 1]);
        }
    }
}

// ---------------- main fused pair-MLP kernel --------------------------------
__global__ void __launch_bounds__(128, 4) pair_mlp_kernel(
    const float* __restrict__ mask, const float* __restrict__ b3p,
    float* __restrict__ out) {
    extern __shared__ char smem_raw[];
    uint32_t smem_u = smem_to_u32(smem_raw);
    uint32_t base = (smem_u + 1023) & ~1023u;
    char* basep = smem_raw + (base - smem_u);

    const uint32_t OFF_AHI = 0;        // h1 fp16 [128 rows x 128B] 16 KB
    const uint32_t OFF_BHI = 16384;    // W2^T fp16 [64 x 128B]      8 KB

    int tid = threadIdx.x;
    int l = tid & 31;
    int wb = (tid >> 5) << 5;          // warp's 32-row slice base

    // copy pre-swizzled W2 into smem (startup only)
    {
        uint4* ph = (uint4*)(basep + OFF_BHI);
        const uint4* shi = (const uint4*)g_w2hi;
#pragma unroll
        for (int t = 0; t < 4; t++) ph[tid + 128 * t] = __ldg(shi + tid + 128 * t);
    }
    __syncthreads();

    float b3 = __ldg(b3p);
    int arow_lo = ((l >> 3) & 1) * 8 + (l & 7);
    int asel = l >> 4;
    int brow = (l & 7);
    int bnb_hi = (l >> 4) & 1;
    int bchunk = (l >> 3) & 1;
    int c4 = l & 3;

    // W3 B-fragments (constant per lane, resident): replicated across n so
    // output column 0 carries the true dot
    uint32_t w3f0[4], w3f1[4];
#pragma unroll
    for (int p = 0; p < 4; p++) {
        w3f0[p] = c_h2[64 + 8 * p + c4];
        w3f1[p] = c_h2[64 + 8 * p + c4 + 4];
    }

    // chunked schedule: consecutive tiles share jbase -> Bt block L1-resident
    int t0 = (int)(((long long)blockIdx.x * NUM_TILES) / GRID_MAIN);
    int t1 = (int)(((long long)(blockIdx.x + 1) * NUM_TILES) / GRID_MAIN);

    for (int T = t0; T < t1; T++) {
        int i = T & 1023;
        int jbase = (T >> 10) << 7;

        const float4* Ar = (const float4*)(g_A + i * 64);
        const float4* Br = (const float4*)g_Bt + (size_t)(T >> 10) * 2048 + tid;

        // ---- layer 1: fp32 dot for stats; x packed to half2 regs -----------
        float d0 = 0, d1 = 0, d2 = 0, d3 = 0;
        uint32_t xh[32];
#pragma unroll
        for (int t = 0; t < 16; t++) {
            float4 a = __ldg(Ar + t);
            float4 b = __ldg(Br + t * 128);        // coalesced: lane = row
            d0 = fmaf(a.x, b.x, d0); d1 = fmaf(a.y, b.y, d1);
            d2 = fmaf(a.z, b.z, d2); d3 = fmaf(a.w, b.w, d3);
            xh[2 * t]     = h2bits(__floats2half2_rn(a.x + b.x, a.y + b.y));
            xh[2 * t + 1] = h2bits(__floats2half2_rn(a.z + b.z, a.w + b.w));
        }
        float2 stA = __ldg(g_stA + i);
        float2 stB = __ldg(g_stB + jbase + tid);
        float dot = (d0 + d1) + (d2 + d3);
        float m  = (stA.x + stB.x) * (1.f / 64.f);
        float v  = (stA.y + stB.y + 2.f * dot) * (1.f / 64.f) - m * m;
        float rs = rsqrtf(v + 1e-5f);
        float nm = -m * rs;

        // LN1 + ReLU in half2, STS to warp-private rows
        __half2 rsh = __float2half2_rn(rs);
        __half2 nmh = __float2half2_rn(nm);
        __half2 z2 = __float2half2_rn(0.f);
#pragma unroll
        for (int c = 0; c < 8; c++) {
            uint32_t hiw[4];
#pragma unroll
            for (int u = 0; u < 4; u++) {
                int k2 = 4 * c + u;
                __half2 u0 = __hfma2(bits2h(xh[k2]), rsh, nmh);
                __half2 h = __hmax2(__hfma2(u0, bits2h(c_h2[k2]),
                                            bits2h(c_h2[32 + k2])), z2);
                hiw[u] = h2bits(h);
            }
            int off = swz(tid, c);
            *(uint4*)(basep + OFF_AHI + off) = make_uint4(hiw[0], hiw[1], hiw[2], hiw[3]);
        }
        __syncwarp();   // warp-private rows: only intra-warp visibility needed

        // ---- layer 2 GEMM: single-pass fp16, b2 in accumulator init --------
        float acc[2][8][4];
#pragma unroll
        for (int nb = 0; nb < 8; nb++) {
            float2 bb = c_b2[nb * 4 + c4];         // (b2[col], b2[col+1])
            acc[0][nb][0] = bb.x; acc[0][nb][1] = bb.y;
            acc[0][nb][2] = bb.x; acc[0][nb][3] = bb.y;
            acc[1][nb][0] = bb.x; acc[1][nb][1] = bb.y;
            acc[1][nb][2] = bb.x; acc[1][nb][3] = bb.y;
        }
#pragma unroll
        for (int kc = 0; kc < 4; kc++) {
            uint32_t ahi0[4], ahi1[4];
            ldm_x4(ahi0, base + OFF_AHI + swz(wb + arow_lo, kc * 2 + asel));
            ldm_x4(ahi1, base + OFF_AHI + swz(wb + 16 + arow_lo, kc * 2 + asel));
#pragma unroll
            for (int p = 0; p < 4; p++) {
                uint32_t r[4];
                ldm_x4(r, base + OFF_BHI +
                           swz((2 * p + bnb_hi) * 8 + brow, kc * 2 + bchunk));
                mma_f16(acc[0][2 * p],     ahi0, r[0], r[1]);
                mma_f16(acc[1][2 * p],     ahi1, r[0], r[1]);
                mma_f16(acc[0][2 * p + 1], ahi0, r[2], r[3]);
                mma_f16(acc[1][2 * p + 1], ahi1, r[2], r[3]);
            }
        }

        // ---- LN2 stats fp32 (b2 already in acc), shfl reduce ---------------
        float rs0[2], nm0[2], rs1[2], nm1[2];
#pragma unroll
        for (int mf = 0; mf < 2; mf++) {
            float su0 = 0, qu0 = 0, su1 = 0, qu1 = 0;
#pragma unroll
            for (int nb = 0; nb < 8; nb++) {
                float a0 = acc[mf][nb][0], a1 = acc[mf][nb][1];
                float a2 = acc[mf][nb][2], a3 = acc[mf][nb][3];
                su0 += a0 + a1; qu0 = fmaf(a0, a0, fmaf(a1, a1, qu0));
                su1 += a2 + a3; qu1 = fmaf(a2, a2, fmaf(a3, a3, qu1));
            }
            su0 += __shfl_xor_sync(0xffffffffu, su0, 1);
            su0 += __shfl_xor_sync(0xffffffffu, su0, 2);
            qu0 += __shfl_xor_sync(0xffffffffu, qu0, 1);
            qu0 += __shfl_xor_sync(0xffffffffu, qu0, 2);
            su1 += __shfl_xor_sync(0xffffffffu, su1, 1);
            su1 += __shfl_xor_sync(0xffffffffu, su1, 2);
            qu1 += __shfl_xor_sync(0xffffffffu, qu1, 1);
            qu1 += __shfl_xor_sync(0xffffffffu, qu1, 2);
            float m0 = su0 * (1.f / 64.f);
            float v0 = qu0 * (1.f / 64.f) - m0 * m0;
            rs0[mf] = rsqrtf(v0 + 1e-5f); nm0[mf] = -m0 * rs0[mf];
            float m1 = su1 * (1.f / 64.f);
            float v1 = qu1 * (1.f / 64.f) - m1 * m1;
            rs1[mf] = rsqrtf(v1 + 1e-5f); nm1[mf] = -m1 * rs1[mf];
        }

        // ---- y = relu(LN2) in half2 -> W3 dot via mma (b3 in acc init) -----
        float w00, w01, w10, w11;
#pragma unroll
        for (int mf = 0; mf < 2; mf++) {
            float c2[4] = {b3, b3, b3, b3};
            __half2 rg = __float2half2_rn(rs0[mf]), ng = __float2half2_rn(nm0[mf]);
            __half2 r8 = __float2half2_rn(rs1[mf]), n8 = __float2half2_rn(nm1[mf]);
#pragma unroll
            for (int p = 0; p < 4; p++) {
                int nA = 2 * p, nB = 2 * p + 1;
                int kA = nA * 4 + c4, kB = nB * 4 + c4;   // half2 col-pair idx
                __half2 gA = bits2h(c_h2[96 + kA]), bA = bits2h(c_h2[128 + kA]);
                __half2 gB = bits2h(c_h2[96 + kB]), bB = bits2h(c_h2[128 + kB]);
                uint32_t af[4];
                __half2 zz, uu;
                zz = __floats2half2_rn(acc[mf][nA][0], acc[mf][nA][1]);
                uu = __hfma2(zz, rg, ng);
                af[0] = h2bits(__hmax2(__hfma2(uu, gA, bA), z2));
                zz = __floats2half2_rn(acc[mf][nA][2], acc[mf][nA][3]);
                uu = __hfma2(zz, r8, n8);
                af[1] = h2bits(__hmax2(__hfma2(uu, gA, bA), z2));
                zz = __floats2half2_rn(acc[mf][nB][0], acc[mf][nB][1]);
                uu = __hfma2(zz, rg, ng);
                af[2] = h2bits(__hmax2(__hfma2(uu, gB, bB), z2));
                zz = __floats2half2_rn(acc[mf][nB][2], acc[mf][nB][3]);
                uu = __hfma2(zz, r8, n8);
                af[3] = h2bits(__hmax2(__hfma2(uu, gB, bB), z2));
                mma_f16(c2, af, w3f0[p], w3f1[p]);
            }
            if (mf == 0) { w00 = c2[0]; w01 = c2[2]; }
            else         { w10 = c2[0]; w11 = c2[2]; }
        }

        // gather so lane l holds row wb+l -> coalesced mask load + store
        int src = (l & 7) * 4;
        float a0 = __shfl_sync(0xffffffffu, w00, src);
        float a1 = __shfl_sync(0xffffffffu, w01, src);
        float a2 = __shfl_sync(0xffffffffu, w10, src);
        float a3 = __shfl_sync(0xffffffffu, w11, src);
        float dv = (l < 8) ? a0 : (l < 16) ? a1 : (l < 24) ? a2 : a3;
        int jj = jbase + wb + l;
        int p = (i << 10) + jj;
        float sc = dv * __ldg(mask + p);
        out[p] = (jj == i) ? 0.f : sc;

        __syncwarp();   // lanes rejoin before next tile's STS to the warp slice
    }
}

// ---------------- launch ----------------------------------------------------
extern "C" void kernel_launch(void* const* d_in, const int* in_sizes, int n_in,
                              void* d_out, int out_size) {
    const float* emb  = (const float*)d_in[0];
    const float* mask = (const float*)d_in[1];
    const float* W1   = (const float*)d_in[2];
    const float* b1   = (const float*)d_in[3];
    const float* g1   = (const float*)d_in[4];
    const float* be1  = (const float*)d_in[5];
    const float* W2   = (const float*)d_in[6];
    const float* b2   = (const float*)d_in[7];
    const float* g2   = (const float*)d_in[8];
    const float* be2  = (const float*)d_in[9];
    const float* W3   = (const float*)d_in[10];
    const float* b3   = (const float*)d_in[11];
    float* out = (float*)d_out;

    cudaFuncSetAttribute(pair_mlp_kernel,
                         cudaFuncAttributeMaxDynamicSharedMemorySize, SMEM_BYTES);

    precompute_all<<<130, 512>>>(emb, W1, b1, W2, g1, be1, g2, be2, W3, b2);

    // stage packed consts into __constant__ (async D2D copies, capturable)
    void* ph2 = nullptr; void* pb2 = nullptr;
    cudaGetSymbolAddress(&ph2, g_h2d);
    cudaGetSymbolAddress(&pb2, g_b2d);
    cudaMemcpyToSymbolAsync(c_h2, ph2, 160 * sizeof(uint32_t), 0,
                            cudaMemcpyDeviceToDevice, 0);
    cudaMemcpyToSymbolAsync(c_b2, pb2, 32 * sizeof(float2), 0,
                            cudaMemcpyDeviceToDevice, 0);

    pair_mlp_kernel<<<GRID_MAIN, 128, SMEM_BYTES>>>(mask, b3, out);
}